// round 2
// baseline (speedup 1.0000x reference)
#include <cuda_runtime.h>
#include <math.h>

#define Bn 4
#define Cc 256
#define Hh 64
#define Wp 64
#define Nn 4096
#define Mm (Bn*Nn)   // 16384

typedef unsigned long long u64;

__device__ __forceinline__ u64 pack2(float lo, float hi){
    u64 r; asm("mov.b64 %0, {%1,%2};" : "=l"(r) : "f"(lo), "f"(hi)); return r;
}
__device__ __forceinline__ void fma2(u64 &d, u64 a, u64 b){
    asm("fma.rn.f32x2 %0, %1, %2, %0;" : "+l"(d) : "l"(a), "l"(b));
}
__device__ __forceinline__ void unpack2(u64 v, float &lo, float &hi){
    asm("mov.b64 {%0,%1}, %2;" : "=f"(lo), "=f"(hi) : "l"(v));
}

// ---------------- scratch (device globals; no allocation) ----------------
__device__ float d_xT[Bn*Nn*Cc];   // x transposed to [B,N,C]
__device__ float d_q [Bn*Nn*Cc];   // theta rows
__device__ float d_kk[Bn*Nn*Cc];   // phi rows
__device__ float d_gg[Bn*Nn*Cc];   // g rows
__device__ float d_y [Bn*Nn*Cc];   // attention output [B,N,C]
__device__ float d_wy[Bn*Nn*Cc];   // W_y (NHWC)
__device__ float d_t1[Bn*Nn*Cc];
__device__ float d_t2[Bn*Nn*Cc];
__device__ float d_mk[Bn*Nn];
__device__ int   d_act[Bn*Nn];
__device__ int   d_cnt[Bn];
__device__ float d_w1x1[4*Cc*Cc];      // gT, thetaT, phiT, WT  ([c][o])
__device__ float d_wcv[6*9*Cc*Cc];     // conv weights [conv][tap][c][o]
__device__ float d_part[Bn*32*Cc*2];
__device__ float d_mean[Bn*Cc];
__device__ float d_rstd[Bn*Cc];

// ---------------- weight transpose ----------------
__global__ void k_wt(const float* __restrict__ gw, const float* __restrict__ tw,
                     const float* __restrict__ pw, const float* __restrict__ WW,
                     const float* __restrict__ rw1, const float* __restrict__ rw2) {
    __shared__ float tile[32][33];
    int z = blockIdx.z;
    int o0 = blockIdx.x*32, c0 = blockIdx.y*32;
    int tx = threadIdx.x, ty = threadIdx.y;
    if (z < 4) {
        const float* src = (z==0) ? gw : (z==1) ? tw : (z==2) ? pw : WW;
        tile[ty][tx] = src[(o0+ty)*Cc + c0+tx];
        __syncthreads();
        d_w1x1[z*Cc*Cc + (c0+ty)*Cc + (o0+tx)] = tile[tx][ty];
    } else {
        int id = z-4; int cv = id/9, tap = id%9;
        int i = cv>>1; const float* rw = (cv&1) ? rw2 : rw1;
        tile[ty][tx] = rw[(((i*Cc)+(o0+ty))*Cc + (c0+tx))*9 + tap];
        __syncthreads();
        d_wcv[(cv*9+tap)*Cc*Cc + (c0+ty)*Cc + (o0+tx)] = tile[tx][ty];
    }
}

// ---------------- x: NCHW -> [B,N,C] ----------------
__global__ void k_xt(const float* __restrict__ x) {
    __shared__ float tile[32][33];
    int b = blockIdx.z; int n0 = blockIdx.x*32, c0 = blockIdx.y*32;
    int tx = threadIdx.x, ty = threadIdx.y;
    tile[ty][tx] = x[((size_t)(b*Cc) + c0+ty)*Nn + n0+tx];
    __syncthreads();
    d_xT[((size_t)(b*Nn) + n0+ty)*Cc + c0+tx] = tile[tx][ty];
}

// ---------------- mask + deterministic active-key compaction ----------------
__global__ void k_mask(const float* __restrict__ mask) {
    int b = blockIdx.x, t = threadIdx.x;
    __shared__ int sc[1024];
    const float* mb = mask + b*32*32;
    int flag[4]; int cnt = 0;
    #pragma unroll
    for (int i=0;i<4;i++){
        int n = t*4+i; int h = n>>6, w = n&63;
        float fy = h*0.5f - 0.25f, fx = w*0.5f - 0.25f;
        int y0 = (int)floorf(fy), x0 = (int)floorf(fx);
        float wy1 = fy - (float)y0, wx1 = fx - (float)x0;
        int y0c = min(max(y0,0),31), y1c = min(max(y0+1,0),31);
        int x0c = min(max(x0,0),31), x1c = min(max(x0+1,0),31);
        float v = (mb[y0c*32+x0c]*(1.f-wx1) + mb[y0c*32+x1c]*wx1)*(1.f-wy1)
                + (mb[y1c*32+x0c]*(1.f-wx1) + mb[y1c*32+x1c]*wx1)*wy1;
        float mv = (v > 0.f) ? 1.f : v;
        float a = 1.f - mv;
        float tmp = 1.f - mb[(h>>1)*32 + (w>>1)];
        float m = a * tmp;
        d_mk[b*Nn + n] = m;
        flag[i] = (m > 0.5f) ? 1 : 0;
        cnt += flag[i];
    }
    sc[t] = cnt; __syncthreads();
    for (int s=1; s<1024; s<<=1){
        int v = (t >= s) ? sc[t-s] : 0;
        __syncthreads();
        sc[t] += v;
        __syncthreads();
    }
    int base = sc[t] - cnt;
    #pragma unroll
    for (int i=0;i<4;i++) if (flag[i]) d_act[b*Nn + (base++)] = t*4+i;
    if (t == 1023) d_cnt[b] = sc[1023];
}

// ---------------- packed-f32x2 MAC core (shared by gemm & conv) ----------------
__device__ __forceinline__ void mac16(const float (*As)[128], const float (*Bs)[128],
                                      int ty, int tx, u64 acc[8][4]) {
    #pragma unroll
    for (int kk=0; kk<16; kk++){
        float a[8];
        *(float4*)&a[0] = *(const float4*)&As[kk][ty*8];
        *(float4*)&a[4] = *(const float4*)&As[kk][ty*8+4];
        longlong2 b01 = *(const longlong2*)&Bs[kk][tx*8];
        longlong2 b23 = *(const longlong2*)&Bs[kk][tx*8+4];
        u64 bb0 = (u64)b01.x, bb1 = (u64)b01.y, bb2 = (u64)b23.x, bb3 = (u64)b23.y;
        #pragma unroll
        for (int r=0;r<8;r++){
            u64 ar = pack2(a[r], a[r]);
            fma2(acc[r][0], ar, bb0);
            fma2(acc[r][1], ar, bb1);
            fma2(acc[r][2], ar, bb2);
            fma2(acc[r][3], ar, bb3);
        }
    }
}

__device__ __forceinline__ void epilogue(u64 acc[8][4], const float* __restrict__ bias,
                                         float* __restrict__ Cout, int m0, int n0,
                                         int ty, int tx) {
    #pragma unroll
    for (int r=0;r<8;r++){
        int m = m0 + ty*8 + r;
        float o[8];
        #pragma unroll
        for (int j=0;j<4;j++) unpack2(acc[r][j], o[2*j], o[2*j+1]);
        int n = n0 + tx*8;
        float4 v0, v1;
        v0.x = o[0]+bias[n];   v0.y = o[1]+bias[n+1];
        v0.z = o[2]+bias[n+2]; v0.w = o[3]+bias[n+3];
        v1.x = o[4]+bias[n+4]; v1.y = o[5]+bias[n+5];
        v1.z = o[6]+bias[n+6]; v1.w = o[7]+bias[n+7];
        *(float4*)&Cout[(size_t)m*256 + n]   = v0;
        *(float4*)&Cout[(size_t)m*256 + n+4] = v1;
    }
}

// ---------------- SGEMM: C[M,256] = A[M,256] * Bw[256,256] + bias ----------------
__global__ void __launch_bounds__(256) k_gemm(const float* __restrict__ A,
                                              const float* __restrict__ Bw,
                                              const float* __restrict__ bias,
                                              float* __restrict__ Cout) {
    __shared__ float As[16][128];
    __shared__ float Bs[16][128];
    int t = threadIdx.x;
    int tx = t & 15, ty = t >> 4;
    int m0 = blockIdx.y * 128, n0 = blockIdx.x * 128;
    u64 acc[8][4] = {};
    for (int k0 = 0; k0 < 256; k0 += 16) {
        #pragma unroll
        for (int i=0;i<2;i++){
            int f4 = t + i*256;
            int row = f4 >> 2, c4 = (f4 & 3)*4;
            float4 v = *(const float4*)&A[(size_t)(m0+row)*256 + k0 + c4];
            As[c4+0][row]=v.x; As[c4+1][row]=v.y; As[c4+2][row]=v.z; As[c4+3][row]=v.w;
        }
        #pragma unroll
        for (int i=0;i<2;i++){
            int f4 = t + i*256;
            int row = f4 >> 5, c4 = (f4 & 31)*4;
            *(float4*)&Bs[row][c4] = *(const float4*)&Bw[(k0+row)*256 + n0 + c4];
        }
        __syncthreads();
        mac16(As, Bs, ty, tx, acc);
        __syncthreads();
    }
    epilogue(acc, bias, Cout, m0, n0, ty, tx);
}

// ---------------- 3x3 reflect conv as 9 fused tap-GEMMs ----------------
__device__ __forceinline__ int refl(int i, int n){ return i<0 ? -i : (i>=n ? 2*n-2-i : i); }

__global__ void __launch_bounds__(256) k_conv3(const float* __restrict__ A,
                                               const float* __restrict__ Wt,  // [9][256][256]
                                               const float* __restrict__ bias,
                                               float* __restrict__ Cout) {
    __shared__ float As[16][128];
    __shared__ float Bs[16][128];
    int t = threadIdx.x, tx = t & 15, ty = t >> 4;
    int m0 = blockIdx.y * 128, n0 = blockIdx.x * 128;
    u64 acc[8][4] = {};
    for (int tap=0; tap<9; tap++){
        int dy = tap/3 - 1, dx = tap%3 - 1;
        const float* Wb = Wt + tap*Cc*Cc;
        int srow[2];
        #pragma unroll
        for (int i=0;i<2;i++){
            int f4 = t + i*256; int row = f4 >> 2;
            int mg = m0 + row;
            int b = mg >> 12, p = mg & 4095, h = p >> 6, w = p & 63;
            srow[i] = (b<<12) + (refl(h+dy,64)<<6) + refl(w+dx,64);
        }
        for (int k0=0; k0<256; k0+=16){
            #pragma unroll
            for (int i=0;i<2;i++){
                int f4 = t + i*256;
                int row = f4 >> 2, c4 = (f4 & 3)*4;
                float4 v = *(const float4*)&A[(size_t)srow[i]*256 + k0 + c4];
                As[c4+0][row]=v.x; As[c4+1][row]=v.y; As[c4+2][row]=v.z; As[c4+3][row]=v.w;
            }
            #pragma unroll
            for (int i=0;i<2;i++){
                int f4 = t + i*256;
                int row = f4 >> 5, c4 = (f4 & 31)*4;
                *(float4*)&Bs[row][c4] = *(const float4*)&Wb[(k0+row)*256 + n0 + c4];
            }
            __syncthreads();
            mac16(As, Bs, ty, tx, acc);
            __syncthreads();
        }
    }
    epilogue(acc, bias, Cout, m0, n0, ty, tx);
}

// ---------------- masked-softmax attention over compacted keys ----------------
__global__ void __launch_bounds__(256) k_attn() {
    int b = blockIdx.y; int q0 = blockIdx.x * 16;
    __shared__ float Qs[16][257];
    __shared__ float Ks[16][257];
    __shared__ float Gs[16][257];
    __shared__ float Ss[16][17];
    int t = threadIdx.x;
    for (int i=t; i<16*256; i+=256){
        int r = i >> 8, c = i & 255;
        Qs[r][c] = d_q[((size_t)(b*Nn) + q0 + r)*256 + c];
    }
    int cnt = d_cnt[b];
    int q = t >> 4, lane = t & 15;
    float yacc[16];
    #pragma unroll
    for (int i=0;i<16;i++) yacc[i] = 0.f;
    float rmax = -1e30f, rsum = 0.f;
    __syncthreads();
    for (int j0=0; j0<cnt; j0+=16){
        int jn = min(16, cnt - j0);
        for (int i=t; i<jn*256; i+=256){
            int r = i >> 8, c = i & 255;
            int src = d_act[b*Nn + j0 + r];
            Ks[r][c] = d_kk[((size_t)(b*Nn) + src)*256 + c];
            Gs[r][c] = d_gg[((size_t)(b*Nn) + src)*256 + c];
        }
        __syncthreads();
        float s = -1e30f;
        if (lane < jn){
            s = 0.f;
            #pragma unroll 8
            for (int c2=0; c2<256; c2++) s += Qs[q][c2]*Ks[lane][c2];
        }
        Ss[q][lane] = s;
        __syncthreads();
        float cmax = rmax;
        for (int j=0;j<jn;j++) cmax = fmaxf(cmax, Ss[q][j]);
        float scale = expf(rmax - cmax);
        rsum *= scale;
        #pragma unroll
        for (int i=0;i<16;i++) yacc[i] *= scale;
        for (int j=0;j<jn;j++){
            float pj = expf(Ss[q][j] - cmax);
            rsum += pj;
            #pragma unroll
            for (int i=0;i<16;i++) yacc[i] += pj * Gs[j][lane + i*16];
        }
        rmax = cmax;
        __syncthreads();
    }
    float inv = (rsum > 0.f) ? (1.f/rsum) : 0.f;
    #pragma unroll
    for (int i=0;i<16;i++)
        d_y[((size_t)(b*Nn) + q0 + q)*256 + lane + i*16] = yacc[i]*inv;
}

// ---------------- instance-norm stats ----------------
__global__ void k_stat(const float* __restrict__ buf){
    int ch = blockIdx.x, b = blockIdx.y;  // grid (32, B)
    int c = threadIdx.x;
    const float* p = buf + ((size_t)(b*Nn) + ch*128)*256 + c;
    float s = 0.f, s2 = 0.f;
    for (int r=0;r<128;r++){ float v = p[(size_t)r*256]; s += v; s2 += v*v; }
    d_part[((b*32+ch)*256+c)*2+0] = s;
    d_part[((b*32+ch)*256+c)*2+1] = s2;
}
__global__ void k_statf(){
    int b = blockIdx.x, c = threadIdx.x;
    float s=0.f, s2=0.f;
    for (int k=0;k<32;k++){
        s  += d_part[((b*32+k)*256+c)*2+0];
        s2 += d_part[((b*32+k)*256+c)*2+1];
    }
    float mu = s * (1.f/4096.f);
    float var = s2 * (1.f/4096.f) - mu*mu;
    d_mean[b*256+c] = mu;
    d_rstd[b*256+c] = rsqrtf(var + 1e-5f);
}
__global__ void k_in_relu(const float* __restrict__ in, float* __restrict__ out){
    int i = blockIdx.x*256 + threadIdx.x;
    int c = i & 255; int b = i >> 20;
    float v = (in[i] - d_mean[b*256+c]) * d_rstd[b*256+c];
    out[i] = fmaxf(v, 0.f);
}
__global__ void k_in_add(const float* __restrict__ in, float* __restrict__ io){
    int i = blockIdx.x*256 + threadIdx.x;
    int c = i & 255; int b = i >> 20;
    io[i] += (in[i] - d_mean[b*256+c]) * d_rstd[b*256+c];
}

// ---------------- final blend + NHWC->NCHW ----------------
__global__ void k_blend(const float* __restrict__ x, float* __restrict__ z){
    __shared__ float tile[32][33];
    int b = blockIdx.z; int n0 = blockIdx.x*32, c0 = blockIdx.y*32;
    int tx = threadIdx.x, ty = threadIdx.y;
    tile[ty][tx] = d_wy[((size_t)(b*Nn) + n0+ty)*256 + c0+tx];
    __syncthreads();
    int n = n0 + tx, c = c0 + ty;
    float m = d_mk[b*Nn + n];
    size_t idx = ((size_t)(b*Cc + c))*Nn + n;
    z[idx] = m * x[idx] + (1.f - m) * tile[tx][ty];
}

// ---------------- launch ----------------
extern "C" void kernel_launch(void* const* d_in, const int* in_sizes, int n_in,
                              void* d_out, int out_size) {
    (void)in_sizes; (void)n_in; (void)out_size;
    const float* x    = (const float*)d_in[0];
    const float* mask = (const float*)d_in[1];
    const float* g_w  = (const float*)d_in[2];
    const float* g_b  = (const float*)d_in[3];
    const float* th_w = (const float*)d_in[4];
    const float* th_b = (const float*)d_in[5];
    const float* ph_w = (const float*)d_in[6];
    const float* ph_b = (const float*)d_in[7];
    const float* W_w  = (const float*)d_in[8];
    const float* W_b  = (const float*)d_in[9];
    const float* rw1  = (const float*)d_in[10];
    const float* rb1  = (const float*)d_in[11];
    const float* rw2  = (const float*)d_in[12];
    const float* rb2  = (const float*)d_in[13];
    float* z = (float*)d_out;

    float *pxT, *pq, *pk, *pg, *py, *pwy, *pt1, *pt2, *pw1, *pwc;
    cudaGetSymbolAddress((void**)&pxT, d_xT);
    cudaGetSymbolAddress((void**)&pq,  d_q);
    cudaGetSymbolAddress((void**)&pk,  d_kk);
    cudaGetSymbolAddress((void**)&pg,  d_gg);
    cudaGetSymbolAddress((void**)&py,  d_y);
    cudaGetSymbolAddress((void**)&pwy, d_wy);
    cudaGetSymbolAddress((void**)&pt1, d_t1);
    cudaGetSymbolAddress((void**)&pt2, d_t2);
    cudaGetSymbolAddress((void**)&pw1, d_w1x1);
    cudaGetSymbolAddress((void**)&pwc, d_wcv);

    dim3 t32(32,32);
    k_wt  <<<dim3(8,8,58),  t32>>>(g_w, th_w, ph_w, W_w, rw1, rw2);
    k_xt  <<<dim3(128,8,4), t32>>>(x);
    k_mask<<<4, 1024>>>(mask);

    dim3 gg(2,128);
    k_gemm<<<gg,256>>>(pxT, pw1 + 1*Cc*Cc, th_b, pq);   // theta
    k_gemm<<<gg,256>>>(pxT, pw1 + 2*Cc*Cc, ph_b, pk);   // phi
    k_gemm<<<gg,256>>>(pxT, pw1 + 0*Cc*Cc, g_b,  pg);   // g

    k_attn<<<dim3(256,4),256>>>();

    k_gemm<<<gg,256>>>(py, pw1 + 3*Cc*Cc, W_b, pwy);    // W conv1x1

    for (int i=0;i<3;i++){
        k_conv3<<<gg,256>>>(pwy, pwc + (size_t)(2*i)*9*Cc*Cc, rb1 + i*Cc, pt1);
        k_stat <<<dim3(32,4),256>>>(pt1);
        k_statf<<<4,256>>>();
        k_in_relu<<<16384,256>>>(pt1, pt2);
        k_conv3<<<gg,256>>>(pt2, pwc + (size_t)(2*i+1)*9*Cc*Cc, rb2 + i*Cc, pt1);
        k_stat <<<dim3(32,4),256>>>(pt1);
        k_statf<<<4,256>>>();
        k_in_add<<<16384,256>>>(pt1, pwy);
    }

    k_blend<<<dim3(128,8,4), t32>>>(x, z);
}

// round 4
// speedup vs baseline: 1.9024x; 1.9024x over previous
#include <cuda_runtime.h>
#include <cuda_bf16.h>
#include <math.h>
#include <stdint.h>

#define Bn 4
#define Cc 256
#define Nn 4096
#define Mm (Bn*Nn)   // 16384

// ---------------- helpers ----------------
__device__ __forceinline__ uint32_t smem_u32(const void* p){
    uint32_t a;
    asm("{ .reg .u64 t; cvta.to.shared.u64 t, %1; cvt.u32.u64 %0, t; }" : "=r"(a) : "l"(p));
    return a;
}
__device__ __forceinline__ int refl(int i, int n){ return i<0 ? -i : (i>=n ? 2*n-2-i : i); }

__device__ __forceinline__ void cpasync16(uint32_t dst, const void* src){
    asm volatile("cp.async.cg.shared.global [%0], [%1], 16;" :: "r"(dst), "l"(src) : "memory");
}
__device__ __forceinline__ void ldsm4(uint32_t (&r)[4], uint32_t addr){
    asm volatile("ldmatrix.sync.aligned.m8n8.x4.shared.b16 {%0,%1,%2,%3}, [%4];"
        : "=r"(r[0]), "=r"(r[1]), "=r"(r[2]), "=r"(r[3]) : "r"(addr));
}
__device__ __forceinline__ void mma16816(float (&d)[4], const uint32_t (&a)[4], const uint32_t* b){
    asm volatile("mma.sync.aligned.m16n8k16.row.col.f32.bf16.bf16.f32 "
        "{%0,%1,%2,%3},{%4,%5,%6,%7},{%8,%9},{%0,%1,%2,%3};"
        : "+f"(d[0]), "+f"(d[1]), "+f"(d[2]), "+f"(d[3])
        : "r"(a[0]), "r"(a[1]), "r"(a[2]), "r"(a[3]), "r"(b[0]), "r"(b[1]));
}

// ---------------- scratch (device globals) ----------------
__device__ float d_q [Mm*Cc];
__device__ float d_kk[Mm*Cc];
__device__ float d_gg[Mm*Cc];
__device__ float d_wy[Mm*Cc];
__device__ float d_t1[Mm*Cc];
__device__ __nv_bfloat16 d_ah[Mm*Cc];
__device__ __nv_bfloat16 d_al[Mm*Cc];
__device__ __nv_bfloat16 d_ph[Mm*Cc];
__device__ __nv_bfloat16 d_pl[Mm*Cc];
__device__ __nv_bfloat16 d_wbh[6*9*Cc*Cc];
__device__ __nv_bfloat16 d_wbl[6*9*Cc*Cc];
__device__ __nv_bfloat16 d_w1h[4*Cc*Cc];
__device__ __nv_bfloat16 d_w1l[4*Cc*Cc];
__device__ float d_mk[Mm];
__device__ int   d_act[Mm];
__device__ int   d_cnt[Bn];
__device__ float d_part[Bn*32*Cc*2];
__device__ float d_mean[Bn*Cc];
__device__ float d_rstd[Bn*Cc];

// ---------------- weight conversion fp32 -> bf16 hi/lo ----------------
__global__ void k_wconv(const float* __restrict__ rw1, const float* __restrict__ rw2,
                        const float* __restrict__ gw, const float* __restrict__ tw,
                        const float* __restrict__ pw, const float* __restrict__ Ww){
    int idx = blockIdx.x*256 + threadIdx.x;
    const int NC = 6*9*65536;
    float v; __nv_bfloat16 *dh, *dl; int dst;
    if (idx < NC){
        int cv = idx / (9*65536);
        int rem = idx - cv*(9*65536);
        int tap = rem >> 16;
        int oc = rem & 65535;
        int o = oc >> 8, c = oc & 255;
        int i = cv >> 1;
        const float* rw = (cv & 1) ? rw2 : rw1;
        v = rw[(((i*256 + o)*256 + c)*9) + tap];
        dst = idx; dh = d_wbh; dl = d_wbl;
    } else {
        int j = idx - NC;
        int mat = j >> 16;
        int oc = j & 65535;
        const float* src = (mat==0) ? gw : (mat==1) ? tw : (mat==2) ? pw : Ww;
        v = src[oc];
        dst = j; dh = d_w1h; dl = d_w1l;
    }
    __nv_bfloat16 h = __float2bfloat16(v);
    dh[dst] = h;
    dl[dst] = __float2bfloat16(v - __bfloat162float(h));
}

// ---------------- x: NCHW -> bf16 hi/lo [B,N,C] ----------------
__global__ void k_xt(const float* __restrict__ x){
    __shared__ float tile[32][33];
    int b = blockIdx.z; int n0 = blockIdx.x*32, c0 = blockIdx.y*32;
    int tx = threadIdx.x, ty = threadIdx.y;
    tile[ty][tx] = x[((size_t)(b*Cc) + c0+ty)*Nn + n0+tx];
    __syncthreads();
    float v = tile[tx][ty];
    size_t o = ((size_t)(b*Nn) + n0+ty)*Cc + c0+tx;
    __nv_bfloat16 h = __float2bfloat16(v);
    d_ah[o] = h;
    d_al[o] = __float2bfloat16(v - __bfloat162float(h));
}

// ---------------- mask + active-key compaction ----------------
__global__ void k_mask(const float* __restrict__ mask){
    int b = blockIdx.x, t = threadIdx.x;
    __shared__ int sc[1024];
    const float* mb = mask + b*32*32;
    int flag[4]; int cnt = 0;
    #pragma unroll
    for (int i=0;i<4;i++){
        int n = t*4+i; int h = n>>6, w = n&63;
        float fy = h*0.5f - 0.25f, fx = w*0.5f - 0.25f;
        int y0 = (int)floorf(fy), x0 = (int)floorf(fx);
        float wy1 = fy - (float)y0, wx1 = fx - (float)x0;
        int y0c = min(max(y0,0),31), y1c = min(max(y0+1,0),31);
        int x0c = min(max(x0,0),31), x1c = min(max(x0+1,0),31);
        float v = (mb[y0c*32+x0c]*(1.f-wx1) + mb[y0c*32+x1c]*wx1)*(1.f-wy1)
                + (mb[y1c*32+x0c]*(1.f-wx1) + mb[y1c*32+x1c]*wx1)*wy1;
        float mv = (v > 0.f) ? 1.f : v;
        float a = 1.f - mv;
        float tmp = 1.f - mb[(h>>1)*32 + (w>>1)];
        float m = a * tmp;
        d_mk[b*Nn + n] = m;
        flag[i] = (m > 0.5f) ? 1 : 0;
        cnt += flag[i];
    }
    sc[t] = cnt; __syncthreads();
    for (int s=1; s<1024; s<<=1){
        int v = (t >= s) ? sc[t-s] : 0;
        __syncthreads();
        sc[t] += v;
        __syncthreads();
    }
    int base = sc[t] - cnt;
    #pragma unroll
    for (int i=0;i<4;i++) if (flag[i]) d_act[b*Nn + (base++)] = t*4+i;
    if (t == 1023) d_cnt[b] = sc[1023];
}

// ================= warp-MMA bf16 GEMM / 3x3-reflect-conv =================
// out[m][o] = sum_{tap,c} A[srow(m,tap)][c] * W[tap][o][c] + bias[o]
// 3-term hi/lo split accumulated in fp32 via mma.sync m16n8k16 bf16.
#define PADB 80            // bytes per smem row (40 bf16)
#define APLANE 10240       // 128 rows * 80B
#define STAGE (4*APLANE)   // Ah,Al,Bh,Bl
#define TM_SMEM_TOTAL (2*STAGE)  // 81920

__device__ __forceinline__ void tmm_load(uint32_t st,
    const __nv_bfloat16* __restrict__ Ah, const __nv_bfloat16* __restrict__ Al,
    const __nv_bfloat16* __restrict__ Wh, const __nv_bfloat16* __restrict__ Wl,
    int m0, int n0, int tap, int k0, int ntaps, int t)
{
    int dy = tap/3 - 1, dx = tap%3 - 1;
    #pragma unroll
    for (int it=0; it<2; it++){
        int e = t + it*256;
        int r = e >> 2, ch = e & 3;
        int grow;
        if (ntaps > 1){
            int gg = m0 + r, b = gg >> 12, p = gg & 4095, h = p >> 6, w = p & 63;
            grow = (b << 12) + (refl(h+dy,64) << 6) + refl(w+dx,64);
        } else grow = m0 + r;
        size_t src = (size_t)grow*256 + k0 + ch*8;
        uint32_t dst = st + r*PADB + ch*16;
        cpasync16(dst, Ah + src);
        cpasync16(dst + APLANE, Al + src);
    }
    #pragma unroll
    for (int it=0; it<2; it++){
        int e = t + it*256;
        int r = e >> 2, ch = e & 3;
        size_t src = ((size_t)tap*256 + n0 + r)*256 + k0 + ch*8;
        uint32_t dst = st + 2*APLANE + r*PADB + ch*16;
        cpasync16(dst, Wh + src);
        cpasync16(dst + APLANE, Wl + src);
    }
}

__global__ void __launch_bounds__(256)
k_tmm(const __nv_bfloat16* __restrict__ Ah, const __nv_bfloat16* __restrict__ Al,
      const __nv_bfloat16* __restrict__ Wh, const __nv_bfloat16* __restrict__ Wl,
      const float* __restrict__ bias, float* __restrict__ Cout,
      __nv_bfloat16* __restrict__ Oh, __nv_bfloat16* __restrict__ Ol, int ntaps)
{
    extern __shared__ char smem[];
    uint32_t sb = smem_u32(smem);
    int t = threadIdx.x, lane = t & 31, wid = t >> 5;
    int warp_m = wid & 3, warp_n = wid >> 2;
    int n0 = blockIdx.x * 128, m0 = blockIdx.y * 128;

    int S = ntaps * 8;   // k32 chunks
    float acc[2][8][4] = {};

    tmm_load(sb, Ah, Al, Wh, Wl, m0, n0, 0, 0, ntaps, t);
    asm volatile("cp.async.commit_group;" ::: "memory");

    // invariant pieces of ldmatrix lane addresses
    uint32_t aOffL = (uint32_t)((warp_m*32 + (lane & 15))*PADB + (lane >> 4)*16);
    uint32_t bOffL = (uint32_t)((warp_n*64 + (lane & 7) + ((lane >> 4) << 3))*PADB
                                + ((lane >> 3) & 1)*16);

    for (int i = 0; i < S; i++){
        if (i + 1 < S){
            int ni = i + 1;
            tmm_load(sb + (uint32_t)(ni & 1)*STAGE, Ah, Al, Wh, Wl,
                     m0, n0, ni >> 3, (ni & 7)*32, ntaps, t);
            asm volatile("cp.async.commit_group;" ::: "memory");
            asm volatile("cp.async.wait_group 1;" ::: "memory");
        } else {
            asm volatile("cp.async.wait_group 0;" ::: "memory");
        }
        __syncthreads();
        uint32_t st = sb + (uint32_t)(i & 1)*STAGE;
        #pragma unroll
        for (int kk = 0; kk < 2; kk++){
            uint32_t aAddr = st + aOffL + kk*32;
            uint32_t aH[2][4], aL[2][4];
            ldsm4(aH[0], aAddr);
            ldsm4(aH[1], aAddr + 16*PADB);
            ldsm4(aL[0], aAddr + APLANE);
            ldsm4(aL[1], aAddr + APLANE + 16*PADB);
            #pragma unroll
            for (int ng = 0; ng < 2; ng++){
                uint32_t bAddr = st + 2*APLANE + bOffL + ng*32*PADB + kk*32;
                uint32_t bH[8], bL[8];
                ldsm4(*(uint32_t(*)[4])&bH[0], bAddr);
                ldsm4(*(uint32_t(*)[4])&bH[4], bAddr + 16*PADB);
                ldsm4(*(uint32_t(*)[4])&bL[0], bAddr + APLANE);
                ldsm4(*(uint32_t(*)[4])&bL[4], bAddr + APLANE + 16*PADB);
                #pragma unroll
                for (int j = 0; j < 4; j++){
                    int nt = ng*4 + j;
                    #pragma unroll
                    for (int mt = 0; mt < 2; mt++){
                        mma16816(acc[mt][nt], aH[mt], &bH[2*j]);
                        mma16816(acc[mt][nt], aH[mt], &bL[2*j]);
                        mma16816(acc[mt][nt], aL[mt], &bH[2*j]);
                    }
                }
            }
        }
        __syncthreads();
    }

    // ---- epilogue ----
    int rbase = m0 + warp_m*32;
    int nb = n0 + warp_n*64;
    int rr = lane >> 2, c2 = 2*(lane & 3);
    #pragma unroll
    for (int mt = 0; mt < 2; mt++){
        #pragma unroll
        for (int nt = 0; nt < 8; nt++){
            int row = rbase + mt*16 + rr;
            int col = nb + nt*8 + c2;
            float b0 = bias[col], b1 = bias[col+1];
            float v00 = acc[mt][nt][0] + b0, v01 = acc[mt][nt][1] + b1;
            float v10 = acc[mt][nt][2] + b0, v11 = acc[mt][nt][3] + b1;
            float2 p0; p0.x = v00; p0.y = v01;
            float2 p1; p1.x = v10; p1.y = v11;
            *(float2*)&Cout[(size_t)row*256 + col] = p0;
            *(float2*)&Cout[(size_t)(row+8)*256 + col] = p1;
            if (Oh){
                __nv_bfloat16 h00 = __float2bfloat16(v00), h01 = __float2bfloat16(v01);
                __nv_bfloat16 h10 = __float2bfloat16(v10), h11 = __float2bfloat16(v11);
                *(__nv_bfloat162*)&Oh[(size_t)row*256 + col] = __nv_bfloat162(h00, h01);
                *(__nv_bfloat162*)&Oh[(size_t)(row+8)*256 + col] = __nv_bfloat162(h10, h11);
                *(__nv_bfloat162*)&Ol[(size_t)row*256 + col] = __nv_bfloat162(
                    __float2bfloat16(v00 - __bfloat162float(h00)),
                    __float2bfloat16(v01 - __bfloat162float(h01)));
                *(__nv_bfloat162*)&Ol[(size_t)(row+8)*256 + col] = __nv_bfloat162(
                    __float2bfloat16(v10 - __bfloat162float(h10)),
                    __float2bfloat16(v11 - __bfloat162float(h11)));
            }
        }
    }
}

// ---------------- masked-softmax attention over compacted keys ----------------
__global__ void __launch_bounds__(256) k_attn(){
    int b = blockIdx.y; int q0 = blockIdx.x * 16;
    __shared__ float Qs[16][257];
    __shared__ float Ks[16][257];
    __shared__ float Gs[16][257];
    __shared__ float Ss[16][17];
    int t = threadIdx.x;
    for (int i=t; i<16*256; i+=256){
        int r = i >> 8, c = i & 255;
        Qs[r][c] = d_q[((size_t)(b*Nn) + q0 + r)*256 + c];
    }
    int cnt = d_cnt[b];
    int q = t >> 4, lane = t & 15;
    float yacc[16];
    #pragma unroll
    for (int i=0;i<16;i++) yacc[i] = 0.f;
    float rmax = -1e30f, rsum = 0.f;
    __syncthreads();
    for (int j0=0; j0<cnt; j0+=16){
        int jn = min(16, cnt - j0);
        for (int i=t; i<jn*256; i+=256){
            int r = i >> 8, c = i & 255;
            int src = d_act[b*Nn + j0 + r];
            Ks[r][c] = d_kk[((size_t)(b*Nn) + src)*256 + c];
            Gs[r][c] = d_gg[((size_t)(b*Nn) + src)*256 + c];
        }
        __syncthreads();
        float s = -1e30f;
        if (lane < jn){
            s = 0.f;
            #pragma unroll 8
            for (int c2=0; c2<256; c2++) s += Qs[q][c2]*Ks[lane][c2];
        }
        Ss[q][lane] = s;
        __syncthreads();
        float cmax = rmax;
        for (int j=0;j<jn;j++) cmax = fmaxf(cmax, Ss[q][j]);
        float scale = expf(rmax - cmax);
        rsum *= scale;
        #pragma unroll
        for (int i=0;i<16;i++) yacc[i] *= scale;
        for (int j=0;j<jn;j++){
            float pj = expf(Ss[q][j] - cmax);
            rsum += pj;
            #pragma unroll
            for (int i=0;i<16;i++) yacc[i] += pj * Gs[j][lane + i*16];
        }
        rmax = cmax;
        __syncthreads();
    }
    float inv = (rsum > 0.f) ? (1.f/rsum) : 0.f;
    #pragma unroll
    for (int i=0;i<16;i++){
        float v = yacc[i]*inv;
        size_t o = ((size_t)(b*Nn) + q0 + q)*256 + lane + i*16;
        __nv_bfloat16 h = __float2bfloat16(v);
        d_ph[o] = h;
        d_pl[o] = __float2bfloat16(v - __bfloat162float(h));
    }
}

// ---------------- instance-norm ----------------
__global__ void k_stat(const float* __restrict__ buf){
    int ch = blockIdx.x, b = blockIdx.y;
    int c = threadIdx.x;
    const float* p = buf + ((size_t)(b*Nn) + ch*128)*256 + c;
    float s = 0.f, s2 = 0.f;
    for (int r=0;r<128;r++){ float v = p[(size_t)r*256]; s += v; s2 += v*v; }
    d_part[((b*32+ch)*256+c)*2+0] = s;
    d_part[((b*32+ch)*256+c)*2+1] = s2;
}
__global__ void k_statf(){
    int b = blockIdx.x, c = threadIdx.x;
    float s=0.f, s2=0.f;
    for (int k=0;k<32;k++){
        s  += d_part[((b*32+k)*256+c)*2+0];
        s2 += d_part[((b*32+k)*256+c)*2+1];
    }
    float mu = s * (1.f/4096.f);
    float var = s2 * (1.f/4096.f) - mu*mu;
    d_mean[b*256+c] = mu;
    d_rstd[b*256+c] = rsqrtf(var + 1e-5f);
}
__global__ void k_in_relu(const float* __restrict__ in){
    int i = blockIdx.x*256 + threadIdx.x;
    int c = i & 255; int b = i >> 20;
    float v = (in[i] - d_mean[b*256+c]) * d_rstd[b*256+c];
    v = fmaxf(v, 0.f);
    __nv_bfloat16 h = __float2bfloat16(v);
    d_ph[i] = h;
    d_pl[i] = __float2bfloat16(v - __bfloat162float(h));
}
__global__ void k_in_add(const float* __restrict__ in, float* __restrict__ io){
    int i = blockIdx.x*256 + threadIdx.x;
    int c = i & 255; int b = i >> 20;
    float v = io[i] + (in[i] - d_mean[b*256+c]) * d_rstd[b*256+c];
    io[i] = v;
    __nv_bfloat16 h = __float2bfloat16(v);
    d_ah[i] = h;
    d_al[i] = __float2bfloat16(v - __bfloat162float(h));
}

// ---------------- final blend + NHWC->NCHW ----------------
__global__ void k_blend(const float* __restrict__ x, float* __restrict__ z){
    __shared__ float tile[32][33];
    int b = blockIdx.z; int n0 = blockIdx.x*32, c0 = blockIdx.y*32;
    int tx = threadIdx.x, ty = threadIdx.y;
    tile[ty][tx] = d_wy[((size_t)(b*Nn) + n0+ty)*256 + c0+tx];
    __syncthreads();
    int n = n0 + tx, c = c0 + ty;
    float m = d_mk[b*Nn + n];
    size_t idx = ((size_t)(b*Cc + c))*Nn + n;
    z[idx] = m * x[idx] + (1.f - m) * tile[tx][ty];
}

// ---------------- launch ----------------
extern "C" void kernel_launch(void* const* d_in, const int* in_sizes, int n_in,
                              void* d_out, int out_size) {
    (void)in_sizes; (void)n_in; (void)out_size;
    const float* x    = (const float*)d_in[0];
    const float* mask = (const float*)d_in[1];
    const float* g_w  = (const float*)d_in[2];
    const float* g_b  = (const float*)d_in[3];
    const float* th_w = (const float*)d_in[4];
    const float* th_b = (const float*)d_in[5];
    const float* ph_w = (const float*)d_in[6];
    const float* ph_b = (const float*)d_in[7];
    const float* W_w  = (const float*)d_in[8];
    const float* W_b  = (const float*)d_in[9];
    const float* rw1  = (const float*)d_in[10];
    const float* rb1  = (const float*)d_in[11];
    const float* rw2  = (const float*)d_in[12];
    const float* rb2  = (const float*)d_in[13];
    float* z = (float*)d_out;

    cudaFuncSetAttribute(k_tmm, cudaFuncAttributeMaxDynamicSharedMemorySize, TM_SMEM_TOTAL);

    float *pq, *pk, *pg, *pwy, *pt1;
    __nv_bfloat16 *pah, *pal, *pph, *ppl, *pwbh, *pwbl, *pw1h, *pw1l;
    cudaGetSymbolAddress((void**)&pq,  d_q);
    cudaGetSymbolAddress((void**)&pk,  d_kk);
    cudaGetSymbolAddress((void**)&pg,  d_gg);
    cudaGetSymbolAddress((void**)&pwy, d_wy);
    cudaGetSymbolAddress((void**)&pt1, d_t1);
    cudaGetSymbolAddress((void**)&pah, d_ah);
    cudaGetSymbolAddress((void**)&pal, d_al);
    cudaGetSymbolAddress((void**)&pph, d_ph);
    cudaGetSymbolAddress((void**)&ppl, d_pl);
    cudaGetSymbolAddress((void**)&pwbh, d_wbh);
    cudaGetSymbolAddress((void**)&pwbl, d_wbl);
    cudaGetSymbolAddress((void**)&pw1h, d_w1h);
    cudaGetSymbolAddress((void**)&pw1l, d_w1l);

    dim3 t32(32,32);
    k_wconv<<<14848, 256>>>(rw1, rw2, g_w, th_w, ph_w, W_w);
    k_xt  <<<dim3(128,8,4), t32>>>(x);
    k_mask<<<4, 1024>>>(mask);

    dim3 gg(2,128);
    k_tmm<<<gg,256,TM_SMEM_TOTAL>>>(pah, pal, pw1h+1*65536, pw1l+1*65536, th_b, pq, 0, 0, 1);
    k_tmm<<<gg,256,TM_SMEM_TOTAL>>>(pah, pal, pw1h+2*65536, pw1l+2*65536, ph_b, pk, 0, 0, 1);
    k_tmm<<<gg,256,TM_SMEM_TOTAL>>>(pah, pal, pw1h+0*65536, pw1l+0*65536, g_b,  pg, 0, 0, 1);

    k_attn<<<dim3(256,4),256>>>();   // writes y planes into d_ph/d_pl

    k_tmm<<<gg,256,TM_SMEM_TOTAL>>>(pph, ppl, pw1h+3*65536, pw1l+3*65536, W_b, pwy, pah, pal, 1);

    for (int i=0;i<3;i++){
        k_tmm<<<gg,256,TM_SMEM_TOTAL>>>(pah, pal, pwbh + (size_t)(2*i)*9*65536,
                                        pwbl + (size_t)(2*i)*9*65536, rb1 + i*256, pt1, 0, 0, 9);
        k_stat <<<dim3(32,4),256>>>(pt1);
        k_statf<<<4,256>>>();
        k_in_relu<<<16384,256>>>(pt1);
        k_tmm<<<gg,256,TM_SMEM_TOTAL>>>(pph, ppl, pwbh + (size_t)(2*i+1)*9*65536,
                                        pwbl + (size_t)(2*i+1)*9*65536, rb2 + i*256, pt1, 0, 0, 9);
        k_stat <<<dim3(32,4),256>>>(pt1);
        k_statf<<<4,256>>>();
        k_in_add<<<16384,256>>>(pt1, pwy);
    }

    k_blend<<<dim3(128,8,4), t32>>>(x, z);
}